// round 13
// baseline (speedup 1.0000x reference)
#include <cuda_runtime.h>
#include <cuda_bf16.h>
#include <cstdint>

// BoundaryLoss fused kernel, v12: cp.async-staged target tile, full coverage.
//  - block = 512 threads; tile = 512 cols x 16 output rows (20 staged rows,
//    40KB smem) staged via cp.async (LDGSTS): no register landing, whole tile
//    in flight -> deep MLP; 4 blocks/SM = 2048 threads (100% occupancy)
//  - each thread: 1 column-quad (4 cols) x 4 output rows = 16 px
//  - out-of-image rows: cp.async src-size=0 zero-fill; column halo: 4-float
//    zero pads in smem -> branch-free interior compute
//  - compute: 3x LDS.128 per quad-row horizontal 5-sum, register ring
//    vertical 5-sum, fma/MUFU BCE; pred via __ldcs LDG.128
//  - last-block finalize (threadfence + ticket), double accumulation

#define BATCH 32
#define HT 512
#define WD 512
#define ROWS 16                       // output rows per block
#define SROWS (ROWS + 4)              // 20 staged rows
#define SCOLS 520                     // 4 pad + 512 data + 4 pad
#define NTHR 512
#define GRID_Y (HT / ROWS)            // 32
#define NBLK (GRID_Y * BATCH)         // 1024

__device__ double g_partials[NBLK];
__device__ unsigned int g_count;      // zero-init; reset by last block each launch

__device__ __forceinline__ void bce_w(float x, float t, float s, float& acc) {
    // weight: 5 inside boundary band (0 < boxsum < 25), else 1 (boxsum exact int)
    const float w = (s > 0.5f && s < 24.5f) ? 5.0f : 1.0f;
    // BCE(sigmoid(x), t) = softplus(x) - t*x; stable fast-math softplus
    const float sp = __logf(1.0f + __expf(-fabsf(x))) + fmaxf(x, 0.0f);
    acc = fmaf(fmaf(-x, t, sp), w, acc);
}

__global__ __launch_bounds__(NTHR, 4)
void boundary_loss_kernel(const float* __restrict__ pred,
                          const float* __restrict__ target,
                          float* __restrict__ out) {
    __shared__ __align__(16) float sm[SROWS][SCOLS];

    const int tid  = threadIdx.x;        // 0..511
    const int lane = tid & 31;
    const int wid  = tid >> 5;           // 0..15

    const int by = blockIdx.x;           // row-chunk (0..31)
    const int b  = blockIdx.y;           // batch     (0..31)
    const int r_base = by * ROWS - 2;    // first staged row (may be -2)

    const float* tgt = target + (size_t)b * HT * WD;

    // zero the 4-float pads on both sides of every staged row (40 threads)
    if (tid < 2 * SROWS) {
        const int j = tid >> 1, side = tid & 1;
        *(float4*)&sm[j][side ? 516 : 0] = make_float4(0.f, 0.f, 0.f, 0.f);
    }

    // ---- stage 20 target rows via cp.async: 2560 x 16B, 5 per thread ----
    const unsigned int sbase =
        (unsigned int)__cvta_generic_to_shared(&sm[0][4]);
    #pragma unroll
    for (int i = 0; i < 5; i++) {
        const int idx = tid + i * NTHR;       // 0..2559
        const int j   = idx >> 7;             // staged row 0..19
        const int seg = idx & 127;            // 16B segment within row
        const int gr  = r_base + j;
        const bool rv = (unsigned)gr < (unsigned)HT;
        const float* src = tgt + (size_t)(rv ? gr : 0) * WD + seg * 4;
        const unsigned int dst =
            sbase + (unsigned int)(j * SCOLS + seg * 4) * 4u;
        const int sz = rv ? 16 : 0;           // 0 -> zero-fill out-of-image row
        asm volatile("cp.async.cg.shared.global [%0], [%1], 16, %2;\n"
                     :: "r"(dst), "l"(src), "r"(sz));
    }
    asm volatile("cp.async.commit_group;\n");
    asm volatile("cp.async.wait_group 0;\n");
    __syncthreads();

    // ---- compute: each thread owns 4 cols x 4 output rows ----
    const int quad = tid & 127;          // cols c0..c0+3, c0 = 4*quad (0..508)
    const int rg   = tid >> 7;           // row group 0..3
    const int sr0  = rg * 4;             // first smem row of this window
    const float* pbase = pred + (size_t)b * HT * WD
                       + (size_t)(by * ROWS + rg * 4) * WD + quad * 4;

    float4 hring[5];                     // horizontal 5-sums ring
    float4 cen[2];                       // center target quad, 2-step delay
    float acc = 0.0f;

    #pragma unroll
    for (int j2 = 0; j2 < 8; j2++) {
        // horizontal 5-sum from 3 adjacent LDS.128
        const float4* row_ = (const float4*)&sm[sr0 + j2][0];
        const float4 a_ = row_[quad];        // floats 4q   .. 4q+3
        const float4 b_ = row_[quad + 1];    // floats 4q+4 .. 4q+7 (= cols c0..c0+3)
        const float4 d_ = row_[quad + 2];    // floats 4q+8 .. 4q+11
        float4 h;
        h.x = a_.z + a_.w + b_.x + b_.y + b_.z;
        h.y = a_.w + b_.x + b_.y + b_.z + b_.w;
        h.z = b_.x + b_.y + b_.z + b_.w + d_.x;
        h.w = b_.y + b_.z + b_.w + d_.x + d_.y;
        hring[j2 % 5] = h;

        const float4 tc = cen[j2 & 1];       // mid of smem row sr0+j2-2
        cen[j2 & 1] = b_;

        if (j2 >= 4) {
            // vertical 5-sum over ring (exact small-int fp)
            const float sx = (hring[0].x + hring[1].x) + hring[2].x + (hring[3].x + hring[4].x);
            const float sy = (hring[0].y + hring[1].y) + hring[2].y + (hring[3].y + hring[4].y);
            const float sz = (hring[0].z + hring[1].z) + hring[2].z + (hring[3].z + hring[4].z);
            const float sw = (hring[0].w + hring[1].w) + hring[2].w + (hring[3].w + hring[4].w);

            const float4 p = __ldcs((const float4*)(pbase + (size_t)(j2 - 4) * WD));

            bce_w(p.x, tc.x, sx, acc);
            bce_w(p.y, tc.y, sy, acc);
            bce_w(p.z, tc.z, sz, acc);
            bce_w(p.w, tc.w, sw, acc);
        }
    }

    // ---- block reduction: warp fp32 -> smem -> double ----
    #pragma unroll
    for (int off = 16; off > 0; off >>= 1)
        acc += __shfl_xor_sync(0xFFFFFFFFu, acc, off);

    __shared__ float s_warp[16];
    __shared__ unsigned int s_islast;
    if (lane == 0) s_warp[wid] = acc;
    __syncthreads();

    if (tid == 0) {
        double d = 0.0;
        #pragma unroll
        for (int i = 0; i < 16; i++) d += (double)s_warp[i];
        const int bid = blockIdx.x + GRID_Y * blockIdx.y;
        g_partials[bid] = d;
        __threadfence();
        const unsigned int ticket = atomicAdd(&g_count, 1u);
        s_islast = (ticket == NBLK - 1) ? 1u : 0u;
    }
    __syncthreads();

    // ---- last block finalizes ----
    if (s_islast) {
        const volatile double* vp = (const volatile double*)g_partials;
        double d = vp[tid] + vp[tid + NTHR];

        #pragma unroll
        for (int off = 16; off > 0; off >>= 1)
            d += __shfl_xor_sync(0xFFFFFFFFu, d, off);

        __shared__ double s_dw[16];
        if (lane == 0) s_dw[wid] = d;
        __syncthreads();

        if (tid == 0) {
            double tot = 0.0;
            #pragma unroll
            for (int i = 0; i < 16; i++) tot += s_dw[i];
            out[0] = (float)(tot / ((double)BATCH * HT * WD));
            g_count = 0;     // reset for next graph replay
        }
    }
}

extern "C" void kernel_launch(void* const* d_in, const int* in_sizes, int n_in,
                              void* d_out, int out_size) {
    const float* pred   = (const float*)d_in[0];
    const float* target = (const float*)d_in[1];
    float* out = (float*)d_out;

    dim3 grid(GRID_Y, BATCH);    // 32 x 32 = 1024 blocks
    boundary_loss_kernel<<<grid, NTHR>>>(pred, target, out);
}

// round 14
// speedup vs baseline: 1.2162x; 1.2162x over previous
#include <cuda_runtime.h>
#include <cuda_bf16.h>
#include <cstdint>

// BoundaryLoss fused kernel, v13: PIPELINED cp.async-staged target tile.
//  - 512 threads; tile = 512 cols x 16 output rows (20 staged rows, 40KB)
//  - staging: each thread stages 5 rows (rsub + 4k), ONE commit group per row
//    -> row j complete when its stagers' group j>>2 is done
//  - consumption: 4 chunks x 4 output rows; chunk c waits only for staged
//    rows <= 4c+7 (cp.async.wait_group(3-c) + __syncthreads) -> compute
//    overlaps the in-flight tail of the tile
//  - compute: 1 col/thread; horizontal 5-sum = 5 scalar LDS (conflict-free),
//    register ring vertical 5-sum, fma/MUFU BCE; pred via __ldcs LDG.32
//  - last-block finalize (threadfence + ticket), double accumulation

#define BATCH 32
#define HT 512
#define WD 512
#define ROWS 16                       // output rows per block
#define SROWS (ROWS + 4)              // 20 staged rows
#define SCOLS 520                     // 4 pad + 512 data + 4 pad
#define NTHR 512
#define GRID_Y (HT / ROWS)            // 32
#define NBLK (GRID_Y * BATCH)         // 1024

__device__ double g_partials[NBLK];
__device__ unsigned int g_count;      // zero-init; reset by last block each launch

#define CP_WAIT(n) asm volatile("cp.async.wait_group " #n ";\n" ::: "memory")

__device__ __forceinline__ void bce_w(float x, float t, float s, float& acc) {
    // weight: 5 inside boundary band (0 < boxsum < 25), else 1 (boxsum exact int)
    const float w = (s > 0.5f && s < 24.5f) ? 5.0f : 1.0f;
    // BCE(sigmoid(x), t) = softplus(x) - t*x; stable fast-math softplus
    const float sp = __logf(1.0f + __expf(-fabsf(x))) + fmaxf(x, 0.0f);
    acc = fmaf(fmaf(-x, t, sp), w, acc);
}

__global__ __launch_bounds__(NTHR, 4)
void boundary_loss_kernel(const float* __restrict__ pred,
                          const float* __restrict__ target,
                          float* __restrict__ out) {
    __shared__ __align__(16) float sm[SROWS][SCOLS];

    const int tid  = threadIdx.x;        // 0..511
    const int lane = tid & 31;
    const int wid  = tid >> 5;           // 0..15

    const int by = blockIdx.x;           // row-chunk (0..31)
    const int b  = blockIdx.y;           // batch     (0..31)
    const int r_base = by * ROWS - 2;    // first staged row (may be -2)

    const float* tgt = target + (size_t)b * HT * WD;

    // zero the 4-float pads on both sides of every staged row (40 threads)
    if (tid < 2 * SROWS) {
        const int j = tid >> 1, side = tid & 1;
        *(float4*)&sm[j][side ? 516 : 0] = make_float4(0.f, 0.f, 0.f, 0.f);
    }

    // ---- stage 20 rows: thread (rsub, seg) stages rows rsub+4k, one
    //      commit group per row (group k <-> row 4k+rsub) ----
    const int rsub = tid >> 7;           // 0..3
    const int seg  = tid & 127;          // 16B segment within row
    const unsigned int sbase =
        (unsigned int)__cvta_generic_to_shared(&sm[0][4]);
    #pragma unroll
    for (int k = 0; k < 5; k++) {
        const int j  = 4 * k + rsub;     // staged row 0..19
        const int gr = r_base + j;
        const bool rv = (unsigned)gr < (unsigned)HT;
        const float* src = tgt + (size_t)(rv ? gr : 0) * WD + seg * 4;
        const unsigned int dst =
            sbase + (unsigned int)(j * SCOLS + seg * 4) * 4u;
        const int sz = rv ? 16 : 0;      // 0 -> zero-fill out-of-image row
        asm volatile("cp.async.cg.shared.global [%0], [%1], 16, %2;\n"
                     :: "r"(dst), "l"(src), "r"(sz) : "memory");
        asm volatile("cp.async.commit_group;\n" ::: "memory");
    }

    // ---- compute: 1 col/thread, 16 output rows, chunked consumption ----
    const int cc = tid;                  // image column 0..511
    const float* prow = pred + (size_t)b * HT * WD
                      + (size_t)(by * ROWS) * WD + cc;

    // hsum of staged row jr for column cc (smem floats cc+2 .. cc+6)
    #define HS(jr) (sm[jr][cc + 2] + sm[jr][cc + 3] + sm[jr][cc + 4] \
                  + sm[jr][cc + 5] + sm[jr][cc + 6])

    float hr0, hr1, hr2, hr3, hr4;
    float acc = 0.0f;

    #pragma unroll
    for (int c = 0; c < 4; c++) {
        // rows needed this chunk: staged rows <= 4c+7 -> groups <= c+1 done
        if      (c == 0) CP_WAIT(3);
        else if (c == 1) CP_WAIT(2);
        else if (c == 2) CP_WAIT(1);
        else             CP_WAIT(0);
        __syncthreads();

        if (c == 0) {                    // prologue: rows 0..3 of the window
            hr0 = HS(0); hr1 = HS(1); hr2 = HS(2); hr3 = HS(3);
        }

        #pragma unroll
        for (int i = 0; i < 4; i++) {
            const int o = 4 * c + i;     // output row within tile, 0..15
            hr4 = HS(o + 4);

            const float s = (hr0 + hr1) + hr2 + (hr3 + hr4);
            const float t = sm[o + 2][cc + 4];            // center target
            const float x = __ldcs(prow + (size_t)o * WD);

            bce_w(x, t, s, acc);

            hr0 = hr1; hr1 = hr2; hr2 = hr3; hr3 = hr4;   // slide window
        }
    }
    #undef HS

    // ---- block reduction: warp fp32 -> smem -> double ----
    #pragma unroll
    for (int off = 16; off > 0; off >>= 1)
        acc += __shfl_xor_sync(0xFFFFFFFFu, acc, off);

    __shared__ float s_warp[16];
    __shared__ unsigned int s_islast;
    if (lane == 0) s_warp[wid] = acc;
    __syncthreads();

    if (tid == 0) {
        double d = 0.0;
        #pragma unroll
        for (int i = 0; i < 16; i++) d += (double)s_warp[i];
        const int bid = blockIdx.x + GRID_Y * blockIdx.y;
        g_partials[bid] = d;
        __threadfence();
        const unsigned int ticket = atomicAdd(&g_count, 1u);
        s_islast = (ticket == NBLK - 1) ? 1u : 0u;
    }
    __syncthreads();

    // ---- last block finalizes ----
    if (s_islast) {
        const volatile double* vp = (const volatile double*)g_partials;
        double d = vp[tid] + vp[tid + NTHR];

        #pragma unroll
        for (int off = 16; off > 0; off >>= 1)
            d += __shfl_xor_sync(0xFFFFFFFFu, d, off);

        __shared__ double s_dw[16];
        if (lane == 0) s_dw[wid] = d;
        __syncthreads();

        if (tid == 0) {
            double tot = 0.0;
            #pragma unroll
            for (int i = 0; i < 16; i++) tot += s_dw[i];
            out[0] = (float)(tot / ((double)BATCH * HT * WD));
            g_count = 0;     // reset for next graph replay
        }
    }
}

extern "C" void kernel_launch(void* const* d_in, const int* in_sizes, int n_in,
                              void* d_out, int out_size) {
    const float* pred   = (const float*)d_in[0];
    const float* target = (const float*)d_in[1];
    float* out = (float*)d_out;

    dim3 grid(GRID_Y, BATCH);    // 32 x 32 = 1024 blocks
    boundary_loss_kernel<<<grid, NTHR>>>(pred, target, out);
}

// round 15
// speedup vs baseline: 1.4274x; 1.1736x over previous
#include <cuda_runtime.h>
#include <cuda_bf16.h>
#include <cstdint>

// BoundaryLoss fused kernel, v14: persistent multi-tile, double-buffered
// cp.async pipeline (cross-tile overlap).
//  - 256 blocks x 512 threads; each block processes 4 tiles (512 cols x 16
//    output rows). Two 20-row smem buffers (83KB dynamic, 2 blocks/SM).
//  - pipeline: stage t0, stage t1; loop { wait<=1, sync, compute t_i,
//    sync, stage t_{i+2} into freed buffer } -> a full 40KB tile is always
//    in flight while computing -> DRAM stays fed (~70KB/SM outstanding).
//  - compute: 3x LDS.128 per quad-row horizontal 5-sum, register ring
//    vertical 5-sum, fma/MUFU BCE; pred via __ldcs LDG.128 during compute.
//  - out-of-image rows zero-filled by cp.async src-size=0; column pads
//    zeroed once per buffer (never overwritten).
//  - last-block finalize (threadfence + ticket), double accumulation.

#define BATCH 32
#define HT 512
#define WD 512
#define ROWS 16                       // output rows per tile
#define SROWS (ROWS + 4)              // 20 staged rows
#define SCOLS 520                     // 4 pad + 512 data + 4 pad
#define BUFELEMS (SROWS * SCOLS)      // 10400 floats
#define NTHR 512
#define NTILES 1024                   // 32 row-chunks x 32 batches
#define NBLOCKS 256
#define TPB 4                         // tiles per block
#define SMEM_BYTES (2 * BUFELEMS * 4) // 83200

__device__ double g_partials[NBLOCKS];
__device__ unsigned int g_count;      // zero-init; reset by last block each launch

#define CP_WAIT(n) asm volatile("cp.async.wait_group " #n ";\n" ::: "memory")

__device__ __forceinline__ void bce_w(float x, float t, float s, float& acc) {
    // weight: 5 inside boundary band (0 < boxsum < 25), else 1 (boxsum exact int)
    const float w = (s > 0.5f && s < 24.5f) ? 5.0f : 1.0f;
    // BCE(sigmoid(x), t) = softplus(x) - t*x; stable fast-math softplus
    const float sp = __logf(1.0f + __expf(-fabsf(x))) + fmaxf(x, 0.0f);
    acc = fmaf(fmaf(-x, t, sp), w, acc);
}

// stage one 20-row target tile into buf (data region cols [4,516))
__device__ __forceinline__ void stage_tile(float* buf,
                                           const float* __restrict__ target,
                                           int tile, int tid) {
    const int by = tile & 31;
    const int b  = tile >> 5;
    const int r_base = by * ROWS - 2;
    const float* tgt = target + (size_t)b * HT * WD;
    const unsigned int sbase = (unsigned int)__cvta_generic_to_shared(buf + 4);
    #pragma unroll
    for (int i = 0; i < 5; i++) {
        const int idx = tid + i * NTHR;      // 0..2559
        const int j   = idx >> 7;            // staged row 0..19
        const int seg = idx & 127;           // 16B segment
        const int gr  = r_base + j;
        const bool rv = (unsigned)gr < (unsigned)HT;
        const float* src = tgt + (size_t)(rv ? gr : 0) * WD + seg * 4;
        const unsigned int dst =
            sbase + (unsigned int)(j * SCOLS + seg * 4) * 4u;
        const int sz = rv ? 16 : 0;          // 0 -> zero-fill out-of-image row
        asm volatile("cp.async.cg.shared.global [%0], [%1], 16, %2;\n"
                     :: "r"(dst), "l"(src), "r"(sz) : "memory");
    }
    asm volatile("cp.async.commit_group;\n" ::: "memory");
}

// consume one staged tile: this thread's 4 cols x 4 output rows
__device__ __forceinline__ float compute_tile(const float* buf,
                                              const float* __restrict__ pred,
                                              int tile, int quad, int rg) {
    const int by = tile & 31;
    const int b  = tile >> 5;
    const int sr0 = rg * 4;
    const float* pbase = pred + (size_t)b * HT * WD
                       + (size_t)(by * ROWS + rg * 4) * WD + quad * 4;

    float4 hring[5];
    float4 cen[2];
    float acc = 0.0f;

    #pragma unroll
    for (int j2 = 0; j2 < 8; j2++) {
        const float4* row_ = (const float4*)(buf + (sr0 + j2) * SCOLS);
        const float4 a_ = row_[quad];        // floats 4q   .. 4q+3
        const float4 b_ = row_[quad + 1];    // floats 4q+4 .. 4q+7 (cols c0..c0+3)
        const float4 d_ = row_[quad + 2];    // floats 4q+8 .. 4q+11
        float4 h;
        h.x = a_.z + a_.w + b_.x + b_.y + b_.z;
        h.y = a_.w + b_.x + b_.y + b_.z + b_.w;
        h.z = b_.x + b_.y + b_.z + b_.w + d_.x;
        h.w = b_.y + b_.z + b_.w + d_.x + d_.y;
        hring[j2 % 5] = h;

        const float4 tc = cen[j2 & 1];       // mid of staged row sr0+j2-2
        cen[j2 & 1] = b_;

        if (j2 >= 4) {
            const float sx = (hring[0].x + hring[1].x) + hring[2].x + (hring[3].x + hring[4].x);
            const float sy = (hring[0].y + hring[1].y) + hring[2].y + (hring[3].y + hring[4].y);
            const float sz = (hring[0].z + hring[1].z) + hring[2].z + (hring[3].z + hring[4].z);
            const float sw = (hring[0].w + hring[1].w) + hring[2].w + (hring[3].w + hring[4].w);

            const float4 p = __ldcs((const float4*)(pbase + (size_t)(j2 - 4) * WD));

            bce_w(p.x, tc.x, sx, acc);
            bce_w(p.y, tc.y, sy, acc);
            bce_w(p.z, tc.z, sz, acc);
            bce_w(p.w, tc.w, sw, acc);
        }
    }
    return acc;
}

__global__ __launch_bounds__(NTHR, 2)
void boundary_loss_kernel(const float* __restrict__ pred,
                          const float* __restrict__ target,
                          float* __restrict__ out) {
    extern __shared__ __align__(16) float sm[];   // [2][SROWS][SCOLS]

    const int tid  = threadIdx.x;        // 0..511
    const int lane = tid & 31;
    const int wid  = tid >> 5;           // 0..15
    const int blk  = blockIdx.x;         // 0..255

    float* buf0 = sm;
    float* buf1 = sm + BUFELEMS;

    // zero the 4-float pads on both sides of every row, both buffers (once;
    // cp.async only ever writes the data region)
    if (tid < 4 * SROWS) {
        const int bi = tid / (2 * SROWS);
        const int r  = (tid % (2 * SROWS)) >> 1;
        const int side = tid & 1;
        float* bb = bi ? buf1 : buf0;
        *(float4*)(bb + r * SCOLS + (side ? 516 : 0)) =
            make_float4(0.f, 0.f, 0.f, 0.f);
    }

    const int quad = tid & 127;          // column quad (cols 4q..4q+3)
    const int rg   = tid >> 7;           // row group 0..3

    // ---- software pipeline over 4 tiles: blk, blk+256, blk+512, blk+768 ----
    stage_tile(buf0, target, blk + 0 * NBLOCKS, tid);
    stage_tile(buf1, target, blk + 1 * NBLOCKS, tid);

    float acc = 0.0f;
    #pragma unroll
    for (int i = 0; i < TPB; i++) {
        if (i < TPB - 1) CP_WAIT(1); else CP_WAIT(0);
        __syncthreads();                 // staged data (and pads) visible

        float* cur = (i & 1) ? buf1 : buf0;
        acc += compute_tile(cur, pred, blk + i * NBLOCKS, quad, rg);

        if (i + 2 < TPB) {
            __syncthreads();             // everyone done reading cur
            stage_tile(cur, target, blk + (i + 2) * NBLOCKS, tid);
        }
    }

    // ---- block reduction: warp fp32 -> smem -> double ----
    #pragma unroll
    for (int off = 16; off > 0; off >>= 1)
        acc += __shfl_xor_sync(0xFFFFFFFFu, acc, off);

    __shared__ float s_warp[16];
    __shared__ unsigned int s_islast;
    if (lane == 0) s_warp[wid] = acc;
    __syncthreads();

    if (tid == 0) {
        double d = 0.0;
        #pragma unroll
        for (int i = 0; i < 16; i++) d += (double)s_warp[i];
        g_partials[blk] = d;
        __threadfence();
        const unsigned int ticket = atomicAdd(&g_count, 1u);
        s_islast = (ticket == NBLOCKS - 1) ? 1u : 0u;
    }
    __syncthreads();

    // ---- last block finalizes ----
    if (s_islast) {
        const volatile double* vp = (const volatile double*)g_partials;
        double d = (tid < NBLOCKS) ? vp[tid] : 0.0;

        #pragma unroll
        for (int off = 16; off > 0; off >>= 1)
            d += __shfl_xor_sync(0xFFFFFFFFu, d, off);

        __shared__ double s_dw[16];
        if (lane == 0) s_dw[wid] = d;
        __syncthreads();

        if (tid == 0) {
            double tot = 0.0;
            #pragma unroll
            for (int i = 0; i < 16; i++) tot += s_dw[i];
            out[0] = (float)(tot / ((double)BATCH * HT * WD));
            g_count = 0;     // reset for next graph replay
        }
    }
}

extern "C" void kernel_launch(void* const* d_in, const int* in_sizes, int n_in,
                              void* d_out, int out_size) {
    const float* pred   = (const float*)d_in[0];
    const float* target = (const float*)d_in[1];
    float* out = (float*)d_out;

    cudaFuncSetAttribute(boundary_loss_kernel,
                         cudaFuncAttributeMaxDynamicSharedMemorySize,
                         SMEM_BYTES);
    boundary_loss_kernel<<<NBLOCKS, NTHR, SMEM_BYTES>>>(pred, target, out);
}

// round 16
// speedup vs baseline: 1.5951x; 1.1175x over previous
#include <cuda_runtime.h>
#include <cuda_bf16.h>
#include <cstdint>

// BoundaryLoss fused kernel, v15: v4 geometry + explicit depth-2 software
// pipeline over ALL loads (target quad, halos, AND pred).
//  - 128-thread block = full 512-px row width (4 cols/thread, float4)
//  - streams 20 rows; at iter j: consume stage j (loaded at j-2), refill
//    slot with stage j+2 -> >=8 independent loads in flight per warp,
//    pred included (the stream every earlier variant left latency-exposed)
//  - center target re-loaded from L1 (same addr as 2 iters ago; off the
//    critical path) instead of a register delay ring
//  - vertical 5-sum: running window (+new -old, exact small-int fp)
//  - 1024 blocks, all co-resident: one clean wave
//  - last-block finalize (threadfence + ticket), double accumulation

#define BATCH 32
#define HT 512
#define WD 512
#define ROWS 16                       // output rows per block
#define ITERS (ROWS + 4)              // 20 streamed rows
#define GRID_Y (HT / ROWS)            // 32
#define NBLK (GRID_Y * BATCH)         // 1024

__device__ double g_partials[NBLK];
__device__ unsigned int g_count;      // zero-init; reset by last block each launch

__device__ __forceinline__ void bce_w(float x, float t, float s, float& acc) {
    // weight: 5 inside boundary band (0 < boxsum < 25), else 1 (boxsum exact int)
    const float w = (s > 0.5f && s < 24.5f) ? 5.0f : 1.0f;
    // BCE(sigmoid(x), t) = softplus(x) - t*x; stable fast-math softplus
    const float sp = __logf(1.0f + __expf(-fabsf(x))) + fmaxf(x, 0.0f);
    acc = fmaf(fmaf(-x, t, sp), w, acc);
}

__global__ __launch_bounds__(128, 8)
void boundary_loss_kernel(const float* __restrict__ pred,
                          const float* __restrict__ target,
                          float* __restrict__ out) {
    const int tid  = threadIdx.x;        // 0..127
    const int lane = tid & 31;
    const int wid  = tid >> 5;
    const int c0   = tid * 4;            // this thread's 4 columns

    const int by = blockIdx.x;           // row-chunk (0..31)
    const int b  = blockIdx.y;           // batch     (0..31)
    const int r_base = by * ROWS - 2;    // first streamed row (may be -2)

    // Base pointers at (r_base, c0) / (by*ROWS, c0); deref only under predicate.
    const float* tbase = target + (size_t)b * HT * WD + (ptrdiff_t)r_base * WD + c0;
    const float* pbase = pred   + (size_t)b * HT * WD + (size_t)(by * ROWS) * WD + c0;

    const bool has_left  = (c0 > 0);          // false only for tid 0
    const bool has_right = (c0 + 4 < WD);     // false only for tid 127

    // depth-2 prefetch queue: target quad + halos + pred quad per stage
    float4 q_t[2]; float2 q_l[2]; float2 q_r[2]; float4 q_p[2];

    // PREFETCH stage jj into slot ss. Pred row for stage jj's output is
    // tile row (jj - 4), valid for jj in [4, 19].
    #define PREFETCH(jj, ss) do {                                            \
        const bool rv_ = (unsigned)(r_base + (jj)) < (unsigned)HT;           \
        q_t[ss] = make_float4(0.f, 0.f, 0.f, 0.f);                           \
        q_l[ss] = make_float2(0.f, 0.f);                                     \
        q_r[ss] = make_float2(0.f, 0.f);                                     \
        if (rv_)              q_t[ss] = *(const float4*)(tbase + (jj) * WD); \
        if (rv_ && has_left)  q_l[ss] = *(const float2*)(tbase + (jj) * WD - 2); \
        if (rv_ && has_right) q_r[ss] = *(const float2*)(tbase + (jj) * WD + 4); \
        if ((jj) >= 4)                                                       \
            q_p[ss] = __ldcs((const float4*)(pbase + ((jj) - 4) * WD));      \
    } while (0)

    PREFETCH(0, 0);
    PREFETCH(1, 1);

    float4 hring[5];                     // horizontal 5-sums, rows j-4..j
    float4 vs = make_float4(0.f, 0.f, 0.f, 0.f);
    float acc = 0.0f;

    #pragma unroll
    for (int j = 0; j < ITERS; j++) {
        const int s = j & 1;
        const float4 t  = q_t[s];
        const float2 tL = q_l[s];
        const float2 tR = q_r[s];
        const float4 p  = q_p[s];

        // refill this slot for stage j+2 right away (max prefetch distance)
        if (j + 2 < ITERS) PREFETCH(j + 2, s);

        // horizontal 5-sums (CSE'd, exact small-int arithmetic)
        const float a3 = t.x + t.y + t.z;
        const float a4 = a3 + t.w;
        float4 h;
        h.x = tL.x + tL.y + a3;
        h.y = tL.y + a4;
        h.z = a4 + tR.x;
        h.w = (h.z - t.x) + tR.y;

        // vertical running 5-window
        if (j >= 5) {
            const float4 ho = hring[j % 5];
            vs.x -= ho.x; vs.y -= ho.y; vs.z -= ho.z; vs.w -= ho.w;
        }
        vs.x += h.x; vs.y += h.y; vs.z += h.z; vs.w += h.w;
        hring[j % 5] = h;

        if (j >= 4) {
            // center target quad: same address as stage j-2's load -> L1 hit
            const float4 tc = *(const float4*)(tbase + (j - 2) * WD);

            bce_w(p.x, tc.x, vs.x, acc);
            bce_w(p.y, tc.y, vs.y, acc);
            bce_w(p.z, tc.z, vs.z, acc);
            bce_w(p.w, tc.w, vs.w, acc);
        }
    }
    #undef PREFETCH

    // ---- block reduction: warp fp32 -> smem -> double ----
    #pragma unroll
    for (int off = 16; off > 0; off >>= 1)
        acc += __shfl_xor_sync(0xFFFFFFFFu, acc, off);

    __shared__ float s_warp[4];
    __shared__ unsigned int s_islast;
    if (lane == 0) s_warp[wid] = acc;
    __syncthreads();

    if (tid == 0) {
        double d = (double)s_warp[0] + (double)s_warp[1]
                 + (double)s_warp[2] + (double)s_warp[3];
        const int bid = blockIdx.x + GRID_Y * blockIdx.y;
        g_partials[bid] = d;
        __threadfence();
        const unsigned int ticket = atomicAdd(&g_count, 1u);
        s_islast = (ticket == NBLK - 1) ? 1u : 0u;
    }
    __syncthreads();

    // ---- last block finalizes ----
    if (s_islast) {
        const volatile double* vp = (const volatile double*)g_partials;
        double d = 0.0;
        #pragma unroll
        for (int i = 0; i < NBLK / 128; i++)
            d += vp[tid + i * 128];

        #pragma unroll
        for (int off = 16; off > 0; off >>= 1)
            d += __shfl_xor_sync(0xFFFFFFFFu, d, off);

        __shared__ double s_dw[4];
        if (lane == 0) s_dw[wid] = d;
        __syncthreads();

        if (tid == 0) {
            const double tot = s_dw[0] + s_dw[1] + s_dw[2] + s_dw[3];
            out[0] = (float)(tot / ((double)BATCH * HT * WD));
            g_count = 0;     // reset for next graph replay
        }
    }
}

extern "C" void kernel_launch(void* const* d_in, const int* in_sizes, int n_in,
                              void* d_out, int out_size) {
    const float* pred   = (const float*)d_in[0];
    const float* target = (const float*)d_in[1];
    float* out = (float*)d_out;

    dim3 grid(GRID_Y, BATCH);    // 32 x 32 = 1024 blocks, single clean wave
    boundary_loss_kernel<<<grid, 128>>>(pred, target, out);
}